// round 1
// baseline (speedup 1.0000x reference)
#include <cuda_runtime.h>
#include <math.h>

// Problem constants
#define CDIM 512
#define BATCH 16
#define NPIX 1024            // H*W = 32*32
#define MCOLS (BATCH * NPIX) // 16384

// ---------------------------------------------------------------------------
// Scratch (device globals: allocation-free rule)
// ---------------------------------------------------------------------------
__device__ float g_ht  [(size_t)CDIM * MCOLS];        // 32 MB   groupnorm out, [C][B*N]
__device__ float g_qkv [(size_t)3 * CDIM * MCOLS];    // 96 MB   [3C][B*N]
__device__ float g_attn[(size_t)BATCH * NPIX * NPIX]; // 64 MB   [B][N][N]
__device__ float g_obuf[(size_t)CDIM * MCOLS];        // 32 MB   [C][B*N]

// ---------------------------------------------------------------------------
// GroupNorm: one block per (batch, group). 8 groups of 64 channels.
// Writes transposed layout ht[c][b*N + n] so all GEMMs see K-major contiguity.
// ---------------------------------------------------------------------------
__global__ void groupnorm_kernel(const float* __restrict__ x,
                                 const float* __restrict__ gamma,
                                 const float* __restrict__ beta,
                                 float* __restrict__ ht) {
    const int b = blockIdx.x >> 3;
    const int g = blockIdx.x & 7;
    const float* xb = x + ((size_t)b * CDIM + (size_t)g * 64) * NPIX;
    const int tid = threadIdx.x; // 256 threads
    const int NG = 64 * NPIX;    // 65536 elements per group

    float s = 0.f, ss = 0.f;
    for (int i = tid; i < NG; i += 256) {
        float v = xb[i];
        s += v; ss += v * v;
    }
    #pragma unroll
    for (int o = 16; o > 0; o >>= 1) {
        s  += __shfl_xor_sync(0xffffffffu, s, o);
        ss += __shfl_xor_sync(0xffffffffu, ss, o);
    }
    __shared__ float sh_s[8], sh_ss[8];
    if ((tid & 31) == 0) { sh_s[tid >> 5] = s; sh_ss[tid >> 5] = ss; }
    __syncthreads();
    if (tid < 32) {
        float s2  = (tid < 8) ? sh_s[tid]  : 0.f;
        float ss2 = (tid < 8) ? sh_ss[tid] : 0.f;
        #pragma unroll
        for (int o = 4; o > 0; o >>= 1) {
            s2  += __shfl_xor_sync(0xffffffffu, s2, o);
            ss2 += __shfl_xor_sync(0xffffffffu, ss2, o);
        }
        if (tid == 0) { sh_s[0] = s2; sh_ss[0] = ss2; }
    }
    __syncthreads();
    const float mean = sh_s[0] * (1.f / 65536.f);
    const float var  = sh_ss[0] * (1.f / 65536.f) - mean * mean;
    const float rstd = rsqrtf(var + 1e-5f);

    for (int i = tid; i < NG; i += 256) {
        int c = g * 64 + (i >> 10);
        int n = i & 1023;
        float v = (xb[i] - mean) * rstd;
        v = v * gamma[c] + beta[c];
        ht[(size_t)c * MCOLS + (size_t)b * NPIX + n] = v;
    }
}

// ---------------------------------------------------------------------------
// Generic fp32 SGEMM, 128x128 tile, BK=8, 256 threads, 8x8 per thread.
// Runtime strides let one kernel serve all 4 GEMMs (including transposed
// operand views). Requires: M,N multiples of 128; K multiple of 8;
// the contiguous stride of each operand == 1 (for float4 loads).
//   C[bz, m, n] = alpha * sum_k A[bz, m, k] * B[bz, k, n]  (+bias[m]) (+resid)
// ---------------------------------------------------------------------------
#define BM 128
#define BN 128
#define BK 8
#define TM 8
#define TN 8

__global__ __launch_bounds__(256, 2)
void sgemm_kernel(const float* __restrict__ A, const float* __restrict__ B,
                  float* __restrict__ C,
                  const float* __restrict__ bias, const float* __restrict__ resid,
                  int Kdim,
                  long a_sm, long a_sk, long b_sk, long b_sn,
                  long c_sm, long c_sn,
                  long a_sb, long b_sb, long c_sb,
                  float alpha) {
    __shared__ float As[BK][BM];
    __shared__ float Bs[BK][BN];

    const int bx = blockIdx.x;   // n tile
    const int by = blockIdx.y;   // m tile
    const int bz = blockIdx.z;   // batch

    const float* Ab = A + (size_t)bz * a_sb + (size_t)by * BM * a_sm;
    const float* Bb = B + (size_t)bz * b_sb + (size_t)bx * BN * b_sn;

    const int tid = threadIdx.x;
    const int tx = tid & 15;     // 16 cols of threads
    const int ty = tid >> 4;     // 16 rows of threads

    float acc[TM][TN];
    #pragma unroll
    for (int i = 0; i < TM; i++)
        #pragma unroll
        for (int j = 0; j < TN; j++) acc[i][j] = 0.f;

    for (int k0 = 0; k0 < Kdim; k0 += BK) {
        // ---- load A tile (BM x BK) ----
        if (a_sk == 1) {
            // k contiguous in memory: thread -> (m = tid/2, k4 = (tid&1)*4)
            int m  = tid >> 1;
            int kk = (tid & 1) * 4;
            float4 v = *(const float4*)(Ab + (size_t)m * a_sm + (k0 + kk));
            As[kk + 0][m] = v.x; As[kk + 1][m] = v.y;
            As[kk + 2][m] = v.z; As[kk + 3][m] = v.w;
        } else {
            // m contiguous (a_sm == 1): thread -> (k = tid/32, m4 = (tid&31)*4)
            int kk = tid >> 5;
            int m  = (tid & 31) * 4;
            float4 v = *(const float4*)(Ab + (size_t)(k0 + kk) * a_sk + m);
            As[kk][m + 0] = v.x; As[kk][m + 1] = v.y;
            As[kk][m + 2] = v.z; As[kk][m + 3] = v.w;
        }
        // ---- load B tile (BK x BN) ----
        if (b_sn == 1) {
            int kk = tid >> 5;
            int n  = (tid & 31) * 4;
            float4 v = *(const float4*)(Bb + (size_t)(k0 + kk) * b_sk + n);
            Bs[kk][n + 0] = v.x; Bs[kk][n + 1] = v.y;
            Bs[kk][n + 2] = v.z; Bs[kk][n + 3] = v.w;
        } else {
            // k contiguous (b_sk == 1): thread -> (n = tid/2, k4 = (tid&1)*4)
            int n  = tid >> 1;
            int kk = (tid & 1) * 4;
            float4 v = *(const float4*)(Bb + (size_t)n * b_sn + (k0 + kk));
            Bs[kk + 0][n] = v.x; Bs[kk + 1][n] = v.y;
            Bs[kk + 2][n] = v.z; Bs[kk + 3][n] = v.w;
        }
        __syncthreads();

        #pragma unroll
        for (int kk = 0; kk < BK; kk++) {
            float ar[TM], br[TN];
            #pragma unroll
            for (int i = 0; i < TM; i++) ar[i] = As[kk][ty * TM + i];
            #pragma unroll
            for (int j = 0; j < TN; j++) br[j] = Bs[kk][tx * TN + j];
            #pragma unroll
            for (int i = 0; i < TM; i++)
                #pragma unroll
                for (int j = 0; j < TN; j++)
                    acc[i][j] += ar[i] * br[j];
        }
        __syncthreads();
    }

    // ---- epilogue: alpha, bias (by row), residual, store ----
    #pragma unroll
    for (int i = 0; i < TM; i++) {
        const int m = by * BM + ty * TM + i;
        const float bv = bias ? bias[m] : 0.f;
        #pragma unroll
        for (int j = 0; j < TN; j++) {
            const int n = bx * BN + tx * TN + j;
            size_t off = (size_t)bz * c_sb + (size_t)m * c_sm + (size_t)n * c_sn;
            float v = acc[i][j] * alpha + bv;
            if (resid) v += resid[off];
            C[off] = v;
        }
    }
}

// ---------------------------------------------------------------------------
// Row softmax over attn[B*N rows][N]. One block (256 threads) per row.
// ---------------------------------------------------------------------------
__global__ void softmax_kernel(float* __restrict__ attn) {
    float* row = attn + (size_t)blockIdx.x * NPIX;
    const int tid = threadIdx.x;
    float v[4];
    float mx = -1e30f;
    #pragma unroll
    for (int i = 0; i < 4; i++) {
        v[i] = row[tid + i * 256];
        mx = fmaxf(mx, v[i]);
    }
    #pragma unroll
    for (int o = 16; o > 0; o >>= 1)
        mx = fmaxf(mx, __shfl_xor_sync(0xffffffffu, mx, o));
    __shared__ float sh[8];
    if ((tid & 31) == 0) sh[tid >> 5] = mx;
    __syncthreads();
    if (tid < 32) {
        float m2 = (tid < 8) ? sh[tid] : -1e30f;
        #pragma unroll
        for (int o = 4; o > 0; o >>= 1)
            m2 = fmaxf(m2, __shfl_xor_sync(0xffffffffu, m2, o));
        if (tid == 0) sh[0] = m2;
    }
    __syncthreads();
    mx = sh[0];

    float s = 0.f;
    #pragma unroll
    for (int i = 0; i < 4; i++) {
        v[i] = __expf(v[i] - mx);
        s += v[i];
    }
    #pragma unroll
    for (int o = 16; o > 0; o >>= 1)
        s += __shfl_xor_sync(0xffffffffu, s, o);
    __shared__ float sh2[8];
    if ((tid & 31) == 0) sh2[tid >> 5] = s;
    __syncthreads();
    if (tid < 32) {
        float s2 = (tid < 8) ? sh2[tid] : 0.f;
        #pragma unroll
        for (int o = 4; o > 0; o >>= 1)
            s2 += __shfl_xor_sync(0xffffffffu, s2, o);
        if (tid == 0) sh2[0] = s2;
    }
    __syncthreads();
    const float inv = 1.f / sh2[0];
    #pragma unroll
    for (int i = 0; i < 4; i++) row[tid + i * 256] = v[i] * inv;
}

// ---------------------------------------------------------------------------
// Launch
// ---------------------------------------------------------------------------
extern "C" void kernel_launch(void* const* d_in, const int* in_sizes, int n_in,
                              void* d_out, int out_size) {
    const float* x      = (const float*)d_in[0]; // [16,512,32,32]
    const float* gamma  = (const float*)d_in[1]; // [512]
    const float* beta   = (const float*)d_in[2]; // [512]
    const float* w_qkv  = (const float*)d_in[3]; // [1536,512]
    const float* b_qkv  = (const float*)d_in[4]; // [1536]
    const float* w_proj = (const float*)d_in[5]; // [512,512]
    const float* b_proj = (const float*)d_in[6]; // [512]
    float* out = (float*)d_out;                  // [16,512,32,32]

    float *ht, *qkv, *attn, *obuf;
    cudaGetSymbolAddress((void**)&ht,   g_ht);
    cudaGetSymbolAddress((void**)&qkv,  g_qkv);
    cudaGetSymbolAddress((void**)&attn, g_attn);
    cudaGetSymbolAddress((void**)&obuf, g_obuf);

    const float scale = 1.0f / sqrtf((float)CDIM);

    // 1) GroupNorm -> ht[c][b*N+n]
    groupnorm_kernel<<<BATCH * 8, 256>>>(x, gamma, beta, ht);

    // 2) QKV: qkv[o][m] = w_qkv[o][c] * ht[c][m] + b_qkv[o]
    //    A: (m=o,k=c) sm=512, sk=1   B: (k=c,n=m) sk=16384, sn=1
    sgemm_kernel<<<dim3(MCOLS / BN, (3 * CDIM) / BM, 1), 256>>>(
        w_qkv, ht, qkv, b_qkv, nullptr,
        CDIM, /*a_sm*/ 512, /*a_sk*/ 1, /*b_sk*/ MCOLS, /*b_sn*/ 1,
        /*c_sm*/ MCOLS, /*c_sn*/ 1, 0, 0, 0, 1.0f);

    // 3) Scores: attn[b][i][j] = scale * sum_c q[c,i] * k[c,j]
    //    A = q: (m=i,k=c) sm=1, sk=16384, batch stride 1024
    //    B = k: (k=c,n=j) sk=16384, sn=1, batch stride 1024
    sgemm_kernel<<<dim3(NPIX / BN, NPIX / BM, BATCH), 256>>>(
        qkv, qkv + (size_t)CDIM * MCOLS, attn, nullptr, nullptr,
        CDIM, /*a_sm*/ 1, /*a_sk*/ MCOLS, /*b_sk*/ MCOLS, /*b_sn*/ 1,
        /*c_sm*/ NPIX, /*c_sn*/ 1,
        /*a_sb*/ NPIX, /*b_sb*/ NPIX, /*c_sb*/ (long)NPIX * NPIX, scale);

    // 4) Softmax rows
    softmax_kernel<<<BATCH * NPIX, 256>>>(attn);

    // 5) obuf[c][b*N+i] = sum_j v[c,j] * attn[b][i][j]
    //    A = v: (m=c,k=j) sm=16384, sk=1, batch stride 1024
    //    B = attn^T: (k=j,n=i) sk=1, sn=1024, batch stride N*N
    sgemm_kernel<<<dim3(NPIX / BN, CDIM / BM, BATCH), 256>>>(
        qkv + (size_t)2 * CDIM * MCOLS, attn, obuf, nullptr, nullptr,
        NPIX, /*a_sm*/ MCOLS, /*a_sk*/ 1, /*b_sk*/ 1, /*b_sn*/ NPIX,
        /*c_sm*/ MCOLS, /*c_sn*/ 1,
        /*a_sb*/ NPIX, /*b_sb*/ (long)NPIX * NPIX, /*c_sb*/ NPIX, 1.0f);

    // 6) Proj + bias + residual, store in x layout:
    //    out[b][o][n] = w_proj[o][c]*obuf[c][b*N+n] + b_proj[o] + x[b][o][n]
    sgemm_kernel<<<dim3(NPIX / BN, CDIM / BM, BATCH), 256>>>(
        w_proj, obuf, out, b_proj, x,
        CDIM, /*a_sm*/ 512, /*a_sk*/ 1, /*b_sk*/ MCOLS, /*b_sn*/ 1,
        /*c_sm*/ NPIX, /*c_sn*/ 1,
        /*a_sb*/ 0, /*b_sb*/ NPIX, /*c_sb*/ (long)CDIM * NPIX, 1.0f);
}

// round 2
// speedup vs baseline: 1.7494x; 1.7494x over previous
#include <cuda_runtime.h>
#include <math.h>
#include <stdint.h>

// Problem constants
#define CDIM 512
#define BATCH 16
#define NPIX 1024            // H*W = 32*32
#define MCOLS (BATCH * NPIX) // 16384

// ---------------------------------------------------------------------------
// Scratch (device globals: allocation-free rule)
// ---------------------------------------------------------------------------
__device__ float g_ht  [(size_t)CDIM * MCOLS];        // 32 MB
__device__ float g_qkv [(size_t)3 * CDIM * MCOLS];    // 96 MB
__device__ float g_attn[(size_t)BATCH * NPIX * NPIX]; // 64 MB
__device__ float g_obuf[(size_t)CDIM * MCOLS];        // 32 MB

// ---------------------------------------------------------------------------
// GroupNorm (unchanged from R1)
// ---------------------------------------------------------------------------
__global__ void groupnorm_kernel(const float* __restrict__ x,
                                 const float* __restrict__ gamma,
                                 const float* __restrict__ beta,
                                 float* __restrict__ ht) {
    const int b = blockIdx.x >> 3;
    const int g = blockIdx.x & 7;
    const float* xb = x + ((size_t)b * CDIM + (size_t)g * 64) * NPIX;
    const int tid = threadIdx.x;
    const int NG = 64 * NPIX;

    float s = 0.f, ss = 0.f;
    for (int i = tid; i < NG; i += 256) {
        float v = xb[i];
        s += v; ss += v * v;
    }
    #pragma unroll
    for (int o = 16; o > 0; o >>= 1) {
        s  += __shfl_xor_sync(0xffffffffu, s, o);
        ss += __shfl_xor_sync(0xffffffffu, ss, o);
    }
    __shared__ float sh_s[8], sh_ss[8];
    if ((tid & 31) == 0) { sh_s[tid >> 5] = s; sh_ss[tid >> 5] = ss; }
    __syncthreads();
    if (tid < 32) {
        float s2  = (tid < 8) ? sh_s[tid]  : 0.f;
        float ss2 = (tid < 8) ? sh_ss[tid] : 0.f;
        #pragma unroll
        for (int o = 4; o > 0; o >>= 1) {
            s2  += __shfl_xor_sync(0xffffffffu, s2, o);
            ss2 += __shfl_xor_sync(0xffffffffu, ss2, o);
        }
        if (tid == 0) { sh_s[0] = s2; sh_ss[0] = ss2; }
    }
    __syncthreads();
    const float mean = sh_s[0] * (1.f / 65536.f);
    const float var  = sh_ss[0] * (1.f / 65536.f) - mean * mean;
    const float rstd = rsqrtf(var + 1e-5f);

    for (int i = tid; i < NG; i += 256) {
        int c = g * 64 + (i >> 10);
        int n = i & 1023;
        float v = (xb[i] - mean) * rstd;
        v = v * gamma[c] + beta[c];
        ht[(size_t)c * MCOLS + (size_t)b * NPIX + n] = v;
    }
}

// ---------------------------------------------------------------------------
// TF32 tensor-core GEMM, 128x128x16 tiles, 256 threads (8 warps, 2m x 4n),
// each warp 64x32 via m16n8k8 MMA. Runtime strides serve all 4 GEMMs.
//   C[bz,m,n] = alpha * sum_k A[bz,m,k]*B[bz,k,n] (+bias[m]) (+resid)
// Requires M%128==0, N%128==0, K%16==0, contiguous stride of each operand==1.
// ---------------------------------------------------------------------------
#define BM 128
#define BN 128
#define BK 16
#define LDK 20  // BK + 4 pad -> conflict-free fragment loads

__device__ __forceinline__ uint32_t f2tf32(float f) {
    uint32_t r;
    asm("cvt.rna.tf32.f32 %0, %1;" : "=r"(r) : "f"(f));
    return r;
}

__device__ __forceinline__ void mma_tf32(float c[4], const uint32_t a[4],
                                         const uint32_t b[2]) {
    asm volatile(
        "mma.sync.aligned.m16n8k8.row.col.f32.tf32.tf32.f32 "
        "{%0,%1,%2,%3}, {%4,%5,%6,%7}, {%8,%9}, {%0,%1,%2,%3};\n"
        : "+f"(c[0]), "+f"(c[1]), "+f"(c[2]), "+f"(c[3])
        : "r"(a[0]), "r"(a[1]), "r"(a[2]), "r"(a[3]), "r"(b[0]), "r"(b[1]));
}

__global__ __launch_bounds__(256)
void tf32gemm_kernel(const float* __restrict__ A, const float* __restrict__ B,
                     float* __restrict__ C,
                     const float* __restrict__ bias, const float* __restrict__ resid,
                     int Kdim,
                     long a_sm, long a_sk, long b_sk, long b_sn,
                     long c_sm, long c_sn,
                     long a_sb, long b_sb, long c_sb,
                     float alpha) {
    __shared__ uint32_t As[2][BM][LDK];
    __shared__ uint32_t Bs[2][BN][LDK];

    const int bx = blockIdx.x;
    const int by = blockIdx.y;
    const int bz = blockIdx.z;

    const float* Ab = A + (size_t)bz * a_sb + (size_t)by * BM * a_sm;
    const float* Bb = B + (size_t)bz * b_sb + (size_t)bx * BN * b_sn;

    const int tid  = threadIdx.x;
    const int warp = tid >> 5;
    const int lane = tid & 31;
    const int gid  = lane >> 2;  // 0..7
    const int tig  = lane & 3;   // 0..3
    const int warp_m = (warp & 1) * 64;
    const int warp_n = (warp >> 1) * 32;

    float acc[4][4][4];
    #pragma unroll
    for (int i = 0; i < 4; i++)
        #pragma unroll
        for (int j = 0; j < 4; j++)
            #pragma unroll
            for (int r = 0; r < 4; r++) acc[i][j][r] = 0.f;

    // --- gmem staging (two float4 per operand per iter) ---
    float4 ra0, ra1, rb0, rb1;

    auto load_tile = [&](int k0) {
        if (a_sk == 1) {
            // k contiguous: idx -> (m = idx>>2, k4 = (idx&3)*4)
            const int m  = tid >> 2;
            const int k4 = (tid & 3) * 4;
            ra0 = *(const float4*)(Ab + (size_t)m        * a_sm + (k0 + k4));
            ra1 = *(const float4*)(Ab + (size_t)(m + 64) * a_sm + (k0 + k4));
        } else {
            // m contiguous: idx -> (k = idx>>5, m4 = (idx&31)*4)
            const int k  = tid >> 5;
            const int m4 = (tid & 31) * 4;
            ra0 = *(const float4*)(Ab + (size_t)(k0 + k)     * a_sk + m4);
            ra1 = *(const float4*)(Ab + (size_t)(k0 + k + 8) * a_sk + m4);
        }
        if (b_sk == 1) {
            const int n  = tid >> 2;
            const int k4 = (tid & 3) * 4;
            rb0 = *(const float4*)(Bb + (size_t)n        * b_sn + (k0 + k4));
            rb1 = *(const float4*)(Bb + (size_t)(n + 64) * b_sn + (k0 + k4));
        } else {
            // n contiguous
            const int k  = tid >> 5;
            const int n4 = (tid & 31) * 4;
            rb0 = *(const float4*)(Bb + (size_t)(k0 + k)     * b_sk + n4);
            rb1 = *(const float4*)(Bb + (size_t)(k0 + k + 8) * b_sk + n4);
        }
    };

    auto store_tile = [&](int buf) {
        if (a_sk == 1) {
            const int m  = tid >> 2;
            const int k4 = (tid & 3) * 4;
            uint32_t* p0 = &As[buf][m][k4];
            p0[0] = f2tf32(ra0.x); p0[1] = f2tf32(ra0.y);
            p0[2] = f2tf32(ra0.z); p0[3] = f2tf32(ra0.w);
            uint32_t* p1 = &As[buf][m + 64][k4];
            p1[0] = f2tf32(ra1.x); p1[1] = f2tf32(ra1.y);
            p1[2] = f2tf32(ra1.z); p1[3] = f2tf32(ra1.w);
        } else {
            const int k  = tid >> 5;
            const int m4 = (tid & 31) * 4;
            As[buf][m4 + 0][k] = f2tf32(ra0.x);
            As[buf][m4 + 1][k] = f2tf32(ra0.y);
            As[buf][m4 + 2][k] = f2tf32(ra0.z);
            As[buf][m4 + 3][k] = f2tf32(ra0.w);
            As[buf][m4 + 0][k + 8] = f2tf32(ra1.x);
            As[buf][m4 + 1][k + 8] = f2tf32(ra1.y);
            As[buf][m4 + 2][k + 8] = f2tf32(ra1.z);
            As[buf][m4 + 3][k + 8] = f2tf32(ra1.w);
        }
        if (b_sk == 1) {
            const int n  = tid >> 2;
            const int k4 = (tid & 3) * 4;
            uint32_t* p0 = &Bs[buf][n][k4];
            p0[0] = f2tf32(rb0.x); p0[1] = f2tf32(rb0.y);
            p0[2] = f2tf32(rb0.z); p0[3] = f2tf32(rb0.w);
            uint32_t* p1 = &Bs[buf][n + 64][k4];
            p1[0] = f2tf32(rb1.x); p1[1] = f2tf32(rb1.y);
            p1[2] = f2tf32(rb1.z); p1[3] = f2tf32(rb1.w);
        } else {
            const int k  = tid >> 5;
            const int n4 = (tid & 31) * 4;
            Bs[buf][n4 + 0][k] = f2tf32(rb0.x);
            Bs[buf][n4 + 1][k] = f2tf32(rb0.y);
            Bs[buf][n4 + 2][k] = f2tf32(rb0.z);
            Bs[buf][n4 + 3][k] = f2tf32(rb0.w);
            Bs[buf][n4 + 0][k + 8] = f2tf32(rb1.x);
            Bs[buf][n4 + 1][k + 8] = f2tf32(rb1.y);
            Bs[buf][n4 + 2][k + 8] = f2tf32(rb1.z);
            Bs[buf][n4 + 3][k + 8] = f2tf32(rb1.w);
        }
    };

    load_tile(0);
    store_tile(0);
    __syncthreads();

    int cur = 0;
    for (int k0 = 0; k0 < Kdim; k0 += BK) {
        const bool has_next = (k0 + BK) < Kdim;
        if (has_next) load_tile(k0 + BK);

        // compute on buffer `cur`
        #pragma unroll
        for (int ks = 0; ks < BK; ks += 8) {
            uint32_t af[4][4], bf[4][2];
            #pragma unroll
            for (int i = 0; i < 4; i++) {
                const int m = warp_m + i * 16 + gid;
                af[i][0] = As[cur][m][ks + tig];
                af[i][1] = As[cur][m + 8][ks + tig];
                af[i][2] = As[cur][m][ks + tig + 4];
                af[i][3] = As[cur][m + 8][ks + tig + 4];
            }
            #pragma unroll
            for (int j = 0; j < 4; j++) {
                const int n = warp_n + j * 8 + gid;
                bf[j][0] = Bs[cur][n][ks + tig];
                bf[j][1] = Bs[cur][n][ks + tig + 4];
            }
            #pragma unroll
            for (int i = 0; i < 4; i++)
                #pragma unroll
                for (int j = 0; j < 4; j++)
                    mma_tf32(acc[i][j], af[i], bf[j]);
        }

        if (has_next) store_tile(cur ^ 1);
        __syncthreads();
        cur ^= 1;
    }

    // ---- epilogue ----
    #pragma unroll
    for (int i = 0; i < 4; i++) {
        const int m0 = by * BM + warp_m + i * 16 + gid;
        const float bv0 = bias ? bias[m0] : 0.f;
        const float bv1 = bias ? bias[m0 + 8] : 0.f;
        #pragma unroll
        for (int j = 0; j < 4; j++) {
            const int n0 = bx * BN + warp_n + j * 8 + tig * 2;
            size_t o00 = (size_t)bz * c_sb + (size_t)m0 * c_sm + (size_t)n0 * c_sn;
            size_t o01 = o00 + c_sn;
            size_t o10 = o00 + 8 * c_sm;
            size_t o11 = o10 + c_sn;
            float v0 = acc[i][j][0] * alpha + bv0;
            float v1 = acc[i][j][1] * alpha + bv0;
            float v2 = acc[i][j][2] * alpha + bv1;
            float v3 = acc[i][j][3] * alpha + bv1;
            if (resid) {
                v0 += resid[o00]; v1 += resid[o01];
                v2 += resid[o10]; v3 += resid[o11];
            }
            C[o00] = v0; C[o01] = v1; C[o10] = v2; C[o11] = v3;
        }
    }
}

// ---------------------------------------------------------------------------
// Row softmax (unchanged)
// ---------------------------------------------------------------------------
__global__ void softmax_kernel(float* __restrict__ attn) {
    float* row = attn + (size_t)blockIdx.x * NPIX;
    const int tid = threadIdx.x;
    float v[4];
    float mx = -1e30f;
    #pragma unroll
    for (int i = 0; i < 4; i++) {
        v[i] = row[tid + i * 256];
        mx = fmaxf(mx, v[i]);
    }
    #pragma unroll
    for (int o = 16; o > 0; o >>= 1)
        mx = fmaxf(mx, __shfl_xor_sync(0xffffffffu, mx, o));
    __shared__ float sh[8];
    if ((tid & 31) == 0) sh[tid >> 5] = mx;
    __syncthreads();
    if (tid < 32) {
        float m2 = (tid < 8) ? sh[tid] : -1e30f;
        #pragma unroll
        for (int o = 4; o > 0; o >>= 1)
            m2 = fmaxf(m2, __shfl_xor_sync(0xffffffffu, m2, o));
        if (tid == 0) sh[0] = m2;
    }
    __syncthreads();
    mx = sh[0];

    float s = 0.f;
    #pragma unroll
    for (int i = 0; i < 4; i++) {
        v[i] = __expf(v[i] - mx);
        s += v[i];
    }
    #pragma unroll
    for (int o = 16; o > 0; o >>= 1)
        s += __shfl_xor_sync(0xffffffffu, s, o);
    __shared__ float sh2[8];
    if ((tid & 31) == 0) sh2[tid >> 5] = s;
    __syncthreads();
    if (tid < 32) {
        float s2 = (tid < 8) ? sh2[tid] : 0.f;
        #pragma unroll
        for (int o = 4; o > 0; o >>= 1)
            s2 += __shfl_xor_sync(0xffffffffu, s2, o);
        if (tid == 0) sh2[0] = s2;
    }
    __syncthreads();
    const float inv = 1.f / sh2[0];
    #pragma unroll
    for (int i = 0; i < 4; i++) row[tid + i * 256] = v[i] * inv;
}

// ---------------------------------------------------------------------------
// Launch
// ---------------------------------------------------------------------------
extern "C" void kernel_launch(void* const* d_in, const int* in_sizes, int n_in,
                              void* d_out, int out_size) {
    const float* x      = (const float*)d_in[0];
    const float* gamma  = (const float*)d_in[1];
    const float* beta   = (const float*)d_in[2];
    const float* w_qkv  = (const float*)d_in[3];
    const float* b_qkv  = (const float*)d_in[4];
    const float* w_proj = (const float*)d_in[5];
    const float* b_proj = (const float*)d_in[6];
    float* out = (float*)d_out;

    float *ht, *qkv, *attn, *obuf;
    cudaGetSymbolAddress((void**)&ht,   g_ht);
    cudaGetSymbolAddress((void**)&qkv,  g_qkv);
    cudaGetSymbolAddress((void**)&attn, g_attn);
    cudaGetSymbolAddress((void**)&obuf, g_obuf);

    const float scale = 1.0f / sqrtf((float)CDIM);

    // 1) GroupNorm -> ht[c][b*N+n]
    groupnorm_kernel<<<BATCH * 8, 256>>>(x, gamma, beta, ht);

    // 2) QKV: qkv[o][m] = w_qkv[o][c]*ht[c][m] + b_qkv[o]
    tf32gemm_kernel<<<dim3(MCOLS / BN, (3 * CDIM) / BM, 1), 256>>>(
        w_qkv, ht, qkv, b_qkv, nullptr,
        CDIM, /*a_sm*/ 512, /*a_sk*/ 1, /*b_sk*/ MCOLS, /*b_sn*/ 1,
        /*c_sm*/ MCOLS, /*c_sn*/ 1, 0, 0, 0, 1.0f);

    // 3) Scores: attn[b][i][j] = scale * sum_c q[c,i]*k[c,j]
    tf32gemm_kernel<<<dim3(NPIX / BN, NPIX / BM, BATCH), 256>>>(
        qkv, qkv + (size_t)CDIM * MCOLS, attn, nullptr, nullptr,
        CDIM, /*a_sm*/ 1, /*a_sk*/ MCOLS, /*b_sk*/ MCOLS, /*b_sn*/ 1,
        /*c_sm*/ NPIX, /*c_sn*/ 1,
        /*a_sb*/ NPIX, /*b_sb*/ NPIX, /*c_sb*/ (long)NPIX * NPIX, scale);

    // 4) Softmax rows
    softmax_kernel<<<BATCH * NPIX, 256>>>(attn);

    // 5) obuf[c][b*N+i] = sum_j v[c,j] * attn[b][i][j]
    tf32gemm_kernel<<<dim3(NPIX / BN, CDIM / BM, BATCH), 256>>>(
        qkv + (size_t)2 * CDIM * MCOLS, attn, obuf, nullptr, nullptr,
        NPIX, /*a_sm*/ MCOLS, /*a_sk*/ 1, /*b_sk*/ 1, /*b_sn*/ NPIX,
        /*c_sm*/ MCOLS, /*c_sn*/ 1,
        /*a_sb*/ NPIX, /*b_sb*/ (long)NPIX * NPIX, /*c_sb*/ NPIX, 1.0f);

    // 6) Proj + bias + residual into x layout
    tf32gemm_kernel<<<dim3(NPIX / BN, CDIM / BM, BATCH), 256>>>(
        w_proj, obuf, out, b_proj, x,
        CDIM, /*a_sm*/ 512, /*a_sk*/ 1, /*b_sk*/ MCOLS, /*b_sn*/ 1,
        /*c_sm*/ NPIX, /*c_sn*/ 1,
        /*a_sb*/ 0, /*b_sb*/ NPIX, /*c_sb*/ (long)CDIM * NPIX, 1.0f);
}

// round 5
// speedup vs baseline: 3.0865x; 1.7643x over previous
#include <cuda_runtime.h>
#include <math.h>
#include <stdint.h>

#define CDIM 512
#define BATCH 16
#define NPIX 1024
#define MCOLS (BATCH * NPIX)   // 16384

// ---------------------------------------------------------------------------
// Scratch (device globals)
// ---------------------------------------------------------------------------
__device__ float g_ht    [(size_t)CDIM * MCOLS];         // [c][m] groupnorm out (tf32)
__device__ float g_qkv   [(size_t)3 * CDIM * MCOLS];     // [o][m] (tf32)
__device__ float g_vT    [(size_t)MCOLS * CDIM];         // [tok][c] (tf32)
__device__ float g_attn  [(size_t)BATCH * NPIX * NPIX];  // [b][i][j]
__device__ float g_attnT [(size_t)BATCH * NPIX * NPIX];  // [b][j][i] (tf32)
__device__ float g_obuf  [(size_t)CDIM * MCOLS];         // [c][m] (tf32)
__device__ float g_wqkvT [(size_t)CDIM * 3 * CDIM];      // [c][o] (tf32)
__device__ float g_wprojT[(size_t)CDIM * CDIM];          // [c][o] (tf32)

// ---------------------------------------------------------------------------
// Helpers
// ---------------------------------------------------------------------------
__device__ __forceinline__ float ftf(float f) {  // fp32 -> tf32 (rna), kept in fp32
    uint32_t u; asm("cvt.rna.tf32.f32 %0, %1;" : "=r"(u) : "f"(f));
    return __uint_as_float(u);
}
__device__ __forceinline__ uint32_t sm_u32(const void* p) {
    uint32_t a;
    asm("{ .reg .u64 t; cvta.to.shared.u64 t, %1; cvt.u32.u64 %0, t; }" : "=r"(a) : "l"(p));
    return a;
}
__device__ __forceinline__ void cp16(uint32_t dst, const float* src) {
    asm volatile("cp.async.cg.shared.global [%0], [%1], 16;" :: "r"(dst), "l"(src));
}
__device__ __forceinline__ void mma_tf32(float c[4], const uint32_t a[4],
                                         const uint32_t b[2]) {
    asm volatile(
        "mma.sync.aligned.m16n8k8.row.col.f32.tf32.tf32.f32 "
        "{%0,%1,%2,%3}, {%4,%5,%6,%7}, {%8,%9}, {%0,%1,%2,%3};\n"
        : "+f"(c[0]), "+f"(c[1]), "+f"(c[2]), "+f"(c[3])
        : "r"(a[0]), "r"(a[1]), "r"(a[2]), "r"(a[3]), "r"(b[0]), "r"(b[1]));
}

// ---------------------------------------------------------------------------
// Small kernels
// ---------------------------------------------------------------------------
// batched transpose: in[bz][R][C] -> out[bz][C][R], rounds to tf32
__global__ void transpose_kernel(const float* __restrict__ in, float* __restrict__ out,
                                 int R, int C, long in_bs, long out_bs) {
    __shared__ float t[32][33];
    in  += (size_t)blockIdx.z * in_bs;
    out += (size_t)blockIdx.z * out_bs;
    const int tx = threadIdx.x & 31, ty = threadIdx.x >> 5;
    const int r0 = blockIdx.y * 32, c0 = blockIdx.x * 32;
    #pragma unroll
    for (int k = 0; k < 4; k++)
        t[ty + 8 * k][tx] = in[(size_t)(r0 + ty + 8 * k) * C + c0 + tx];
    __syncthreads();
    #pragma unroll
    for (int k = 0; k < 4; k++)
        out[(size_t)(c0 + ty + 8 * k) * R + r0 + tx] = ftf(t[tx][ty + 8 * k]);
}

__global__ void groupnorm_kernel(const float* __restrict__ x,
                                 const float* __restrict__ gamma,
                                 const float* __restrict__ beta,
                                 float* __restrict__ ht) {
    const int b = blockIdx.x >> 3;
    const int g = blockIdx.x & 7;
    const float* xb = x + ((size_t)b * CDIM + (size_t)g * 64) * NPIX;
    const int tid = threadIdx.x;
    const int NG = 64 * NPIX;

    float s = 0.f, ss = 0.f;
    for (int i = tid; i < NG; i += 256) {
        float v = xb[i];
        s += v; ss += v * v;
    }
    #pragma unroll
    for (int o = 16; o > 0; o >>= 1) {
        s  += __shfl_xor_sync(0xffffffffu, s, o);
        ss += __shfl_xor_sync(0xffffffffu, ss, o);
    }
    __shared__ float sh_s[8], sh_ss[8];
    if ((tid & 31) == 0) { sh_s[tid >> 5] = s; sh_ss[tid >> 5] = ss; }
    __syncthreads();
    if (tid < 32) {
        float s2  = (tid < 8) ? sh_s[tid]  : 0.f;
        float ss2 = (tid < 8) ? sh_ss[tid] : 0.f;
        #pragma unroll
        for (int o = 4; o > 0; o >>= 1) {
            s2  += __shfl_xor_sync(0xffffffffu, s2, o);
            ss2 += __shfl_xor_sync(0xffffffffu, ss2, o);
        }
        if (tid == 0) { sh_s[0] = s2; sh_ss[0] = ss2; }
    }
    __syncthreads();
    const float mean = sh_s[0] * (1.f / 65536.f);
    const float var  = sh_ss[0] * (1.f / 65536.f) - mean * mean;
    const float rstd = rsqrtf(var + 1e-5f);

    for (int i = tid; i < NG; i += 256) {
        int c = g * 64 + (i >> 10);
        int n = i & 1023;
        float v = (xb[i] - mean) * rstd;
        v = v * gamma[c] + beta[c];
        ht[(size_t)c * MCOLS + (size_t)b * NPIX + n] = ftf(v);
    }
}

__global__ void softmax_kernel(float* __restrict__ attn) {
    float* row = attn + (size_t)blockIdx.x * NPIX;
    const int tid = threadIdx.x;
    float v[4];
    float mx = -1e30f;
    #pragma unroll
    for (int i = 0; i < 4; i++) {
        v[i] = row[tid + i * 256];
        mx = fmaxf(mx, v[i]);
    }
    #pragma unroll
    for (int o = 16; o > 0; o >>= 1)
        mx = fmaxf(mx, __shfl_xor_sync(0xffffffffu, mx, o));
    __shared__ float sh[8];
    if ((tid & 31) == 0) sh[tid >> 5] = mx;
    __syncthreads();
    if (tid < 32) {
        float m2 = (tid < 8) ? sh[tid] : -1e30f;
        #pragma unroll
        for (int o = 4; o > 0; o >>= 1)
            m2 = fmaxf(m2, __shfl_xor_sync(0xffffffffu, m2, o));
        if (tid == 0) sh[0] = m2;
    }
    __syncthreads();
    mx = sh[0];

    float s = 0.f;
    #pragma unroll
    for (int i = 0; i < 4; i++) {
        v[i] = __expf(v[i] - mx);
        s += v[i];
    }
    #pragma unroll
    for (int o = 16; o > 0; o >>= 1)
        s += __shfl_xor_sync(0xffffffffu, s, o);
    __shared__ float sh2[8];
    if ((tid & 31) == 0) sh2[tid >> 5] = s;
    __syncthreads();
    if (tid < 32) {
        float s2 = (tid < 8) ? sh2[tid] : 0.f;
        #pragma unroll
        for (int o = 4; o > 0; o >>= 1)
            s2 += __shfl_xor_sync(0xffffffffu, s2, o);
        if (tid == 0) sh2[0] = s2;
    }
    __syncthreads();
    const float inv = 1.f / sh2[0];
    #pragma unroll
    for (int i = 0; i < 4; i++) row[tid + i * 256] = v[i] * inv;
}

// ---------------------------------------------------------------------------
// Pipelined TF32 mma.sync GEMM.
//   D[bz, m, n] = alpha * sum_k A[bz, k, m] * B[bz, k, n] (+bias[m]) (+resid)
// A: k-major rows of contiguous m, row stride a_rs, batch offset a_zs (elems).
// B: k-major rows of contiguous n, row stride b_rs, batch offset b_zs.
// Tile 128x256x16, 256 threads, 8 warps (2m x 4n), warp tile 64x64.
// 3-stage cp.async. Requires M%128==0, N%256==0, K%16==0.
// ---------------------------------------------------------------------------
#define BM 128
#define BN 256
#define BK 16
#define STAGES 3
#define LDA 136   // BM + 8 pad (floats)
#define LDB 264   // BN + 8 pad
#define A_STG (BK * LDA)          // floats per A stage
#define B_STG (BK * LDB)
#define SMEM_FLOATS (STAGES * (A_STG + B_STG))
#define SMEM_BYTES (SMEM_FLOATS * 4)

__global__ __launch_bounds__(256, 1)
void tc_gemm(const float* __restrict__ A, const float* __restrict__ B,
             float* __restrict__ C,
             const float* __restrict__ bias_m, const float* __restrict__ resid,
             int Kdim, long a_rs, long a_zs, long b_rs, long b_zs,
             long c_ms, long c_zs, float alpha, int round_out) {
    extern __shared__ uint32_t smem[];
    uint32_t* Asm = smem;                     // [STAGES][BK][LDA]
    uint32_t* Bsm = smem + STAGES * A_STG;    // [STAGES][BK][LDB]
    const uint32_t as_base = sm_u32(Asm);
    const uint32_t bs_base = sm_u32(Bsm);

    const int tid = threadIdx.x, warp = tid >> 5, lane = tid & 31;
    const int gid = lane >> 2, tig = lane & 3;
    const int bx = blockIdx.x, by = blockIdx.y, bz = blockIdx.z;
    const int wm = (warp & 1) * 64;
    const int wn = (warp >> 1) * 64;

    const float* Ab = A + (size_t)bz * a_zs + (size_t)by * BM;
    const float* Bb = B + (size_t)bz * b_zs + (size_t)bx * BN;

    float acc[4][8][4];
    #pragma unroll
    for (int i = 0; i < 4; i++)
        #pragma unroll
        for (int j = 0; j < 8; j++)
            #pragma unroll
            for (int r = 0; r < 4; r++) acc[i][j][r] = 0.f;

    // fill stage s with k-slice t
    auto fill = [&](int t) {
        const int s = t % STAGES;
        const float* ag = Ab + (size_t)t * BK * a_rs;
        const uint32_t ad = as_base + s * A_STG * 4;
        #pragma unroll
        for (int i = 0; i < 2; i++) {
            int idx = tid + i * 256;           // 512 chunks: k=idx>>5, ch=idx&31
            int k = idx >> 5, m4 = (idx & 31) * 4;
            cp16(ad + (uint32_t)(k * LDA + m4) * 4, ag + (size_t)k * a_rs + m4);
        }
        const float* bg = Bb + (size_t)t * BK * b_rs;
        const uint32_t bd = bs_base + s * B_STG * 4;
        #pragma unroll
        for (int i = 0; i < 4; i++) {
            int idx = tid + i * 256;           // 1024 chunks: k=idx>>6, ch=idx&63
            int k = idx >> 6, n4 = (idx & 63) * 4;
            cp16(bd + (uint32_t)(k * LDB + n4) * 4, bg + (size_t)k * b_rs + n4);
        }
        asm volatile("cp.async.commit_group;" ::: "memory");
    };

    const int T = Kdim / BK;
    fill(0);
    if (T > 1) fill(1);

    for (int t = 0; t < T; t++) {
        if (t < T - 1) asm volatile("cp.async.wait_group 1;" ::: "memory");
        else           asm volatile("cp.async.wait_group 0;" ::: "memory");
        __syncthreads();

        if (t + 2 < T) fill(t + 2);

        const int s = t % STAGES;
        const uint32_t* As = Asm + s * A_STG;
        const uint32_t* Bs = Bsm + s * B_STG;
        #pragma unroll
        for (int ks = 0; ks < BK; ks += 8) {
            const uint32_t* ar0 = As + (ks + tig) * LDA;
            const uint32_t* ar1 = As + (ks + tig + 4) * LDA;
            const uint32_t* br0 = Bs + (ks + tig) * LDB;
            const uint32_t* br1 = Bs + (ks + tig + 4) * LDB;
            uint32_t af[4][4], bf[8][2];
            #pragma unroll
            for (int i = 0; i < 4; i++) {
                const int m = wm + i * 16 + gid;
                af[i][0] = ar0[m];
                af[i][1] = ar0[m + 8];
                af[i][2] = ar1[m];
                af[i][3] = ar1[m + 8];
            }
            #pragma unroll
            for (int j = 0; j < 8; j++) {
                const int n = wn + j * 8 + gid;
                bf[j][0] = br0[n];
                bf[j][1] = br1[n];
            }
            #pragma unroll
            for (int i = 0; i < 4; i++)
                #pragma unroll
                for (int j = 0; j < 8; j++)
                    mma_tf32(acc[i][j], af[i], bf[j]);
        }
        // top-of-loop __syncthreads orders reuse of this stage by fill(t+3)
    }

    // ---- epilogue ----
    #pragma unroll
    for (int i = 0; i < 4; i++) {
        const int m0 = by * BM + wm + i * 16 + gid;
        const float bv0 = bias_m ? bias_m[m0] : 0.f;
        const float bv1 = bias_m ? bias_m[m0 + 8] : 0.f;
        #pragma unroll
        for (int j = 0; j < 8; j++) {
            const int n0 = bx * BN + wn + j * 8 + tig * 2;
            size_t o0 = (size_t)bz * c_zs + (size_t)m0 * c_ms + n0;
            size_t o1 = o0 + 8 * c_ms;
            float2 v0, v1;
            v0.x = acc[i][j][0] * alpha + bv0;
            v0.y = acc[i][j][1] * alpha + bv0;
            v1.x = acc[i][j][2] * alpha + bv1;
            v1.y = acc[i][j][3] * alpha + bv1;
            if (resid) {
                v0.x += resid[o0];     v0.y += resid[o0 + 1];
                v1.x += resid[o1];     v1.y += resid[o1 + 1];
            }
            if (round_out) {
                v0.x = ftf(v0.x); v0.y = ftf(v0.y);
                v1.x = ftf(v1.x); v1.y = ftf(v1.y);
            }
            *(float2*)(C + o0) = v0;
            *(float2*)(C + o1) = v1;
        }
    }
}

// ---------------------------------------------------------------------------
// Launch
// ---------------------------------------------------------------------------
extern "C" void kernel_launch(void* const* d_in, const int* in_sizes, int n_in,
                              void* d_out, int out_size) {
    const float* x      = (const float*)d_in[0];
    const float* gamma  = (const float*)d_in[1];
    const float* beta   = (const float*)d_in[2];
    const float* w_qkv  = (const float*)d_in[3];
    const float* b_qkv  = (const float*)d_in[4];
    const float* w_proj = (const float*)d_in[5];
    const float* b_proj = (const float*)d_in[6];
    float* out = (float*)d_out;

    float *ht, *qkv, *vT, *attn, *attnT, *obuf, *wqkvT, *wprojT;
    cudaGetSymbolAddress((void**)&ht,     g_ht);
    cudaGetSymbolAddress((void**)&qkv,    g_qkv);
    cudaGetSymbolAddress((void**)&vT,     g_vT);
    cudaGetSymbolAddress((void**)&attn,   g_attn);
    cudaGetSymbolAddress((void**)&attnT,  g_attnT);
    cudaGetSymbolAddress((void**)&obuf,   g_obuf);
    cudaGetSymbolAddress((void**)&wqkvT,  g_wqkvT);
    cudaGetSymbolAddress((void**)&wprojT, g_wprojT);

    cudaFuncSetAttribute(tc_gemm, cudaFuncAttributeMaxDynamicSharedMemorySize, SMEM_BYTES);

    const float scale = 1.0f / sqrtf((float)CDIM);

    // 0) transpose + round weights: w_qkv[1536][512] -> wqkvT[512][1536]
    transpose_kernel<<<dim3(512 / 32, 1536 / 32, 1), 256>>>(w_qkv, wqkvT, 1536, 512, 0, 0);
    transpose_kernel<<<dim3(512 / 32, 512 / 32, 1), 256>>>(w_proj, wprojT, 512, 512, 0, 0);

    // 1) GroupNorm -> ht[c][m] (tf32-rounded)
    groupnorm_kernel<<<BATCH * 8, 256>>>(x, gamma, beta, ht);

    // 2) QKV: qkv[o][m] = sum_c wqkvT[c][o] * ht[c][m] + b_qkv[o]
    tc_gemm<<<dim3(MCOLS / BN, 1536 / BM, 1), 256, SMEM_BYTES>>>(
        wqkvT, ht, qkv, b_qkv, nullptr,
        CDIM, /*a_rs*/ 1536, 0, /*b_rs*/ MCOLS, 0,
        /*c_ms*/ MCOLS, 0, 1.0f, /*round*/ 1);

    // 3) Scores: attn[b][i][j] = scale * sum_c q[c][b*1024+i] * k[c][b*1024+j]
    tc_gemm<<<dim3(NPIX / BN, NPIX / BM, BATCH), 256, SMEM_BYTES>>>(
        qkv, qkv + (size_t)CDIM * MCOLS, attn, nullptr, nullptr,
        CDIM, /*a_rs*/ MCOLS, /*a_zs*/ NPIX, /*b_rs*/ MCOLS, /*b_zs*/ NPIX,
        /*c_ms*/ NPIX, (long)NPIX * NPIX, scale, 0);

    // 4) Softmax rows
    softmax_kernel<<<BATCH * NPIX, 256>>>(attn);

    // 5) transposes: attn -> attnT[b][j][i]; v (= qkv rows 1024..1535) -> vT[tok][c]
    transpose_kernel<<<dim3(NPIX / 32, NPIX / 32, BATCH), 256>>>(
        attn, attnT, NPIX, NPIX, (long)NPIX * NPIX, (long)NPIX * NPIX);
    transpose_kernel<<<dim3(MCOLS / 32, CDIM / 32, 1), 256>>>(
        qkv + (size_t)2 * CDIM * MCOLS, vT, CDIM, MCOLS, 0, 0);

    // 6) PV: obuf[c][b*1024+i] = sum_j vT[b*1024+j][c] * attnT[b][j][i]
    tc_gemm<<<dim3(NPIX / BN, CDIM / BM, BATCH), 256, SMEM_BYTES>>>(
        vT, attnT, obuf, nullptr, nullptr,
        NPIX, /*a_rs*/ CDIM, /*a_zs*/ (long)NPIX * CDIM,
        /*b_rs*/ NPIX, /*b_zs*/ (long)NPIX * NPIX,
        /*c_ms*/ MCOLS, /*c_zs*/ NPIX, 1.0f, /*round*/ 1);

    // 7) Proj: out[b][o][n] = sum_c wprojT[c][o] * obuf[c][b*1024+n] + b_proj[o] + x
    tc_gemm<<<dim3(NPIX / BN, CDIM / BM, BATCH), 256, SMEM_BYTES>>>(
        wprojT, obuf, out, b_proj, x,
        CDIM, /*a_rs*/ CDIM, 0, /*b_rs*/ MCOLS, /*b_zs*/ NPIX,
        /*c_ms*/ NPIX, (long)CDIM * NPIX, 1.0f, 0);
}